// round 4
// baseline (speedup 1.0000x reference)
#include <cuda_runtime.h>
#include <cuda_bf16.h>

// AMSoftmaxLoss: score (2048 x 50257) fp32, labels (2048) int32 in {0,1}
// Single balanced wave: 1184 blocks (148 SM x 8), flat partition of all
// 102,926,336 elements. Per-block per-row partial exp-sums -> g_part,
// last block finalizes.

#define NROWS 2048
#define CCOLS 50257
#define NBLK  1184          // 148 SMs * 8 resident blocks
#define BLK   256

#define TOTELEM (NROWS * CCOLS)              // 102,926,336 (fits in int)
#define CHUNK   (TOTELEM / NBLK)             // 86931
#define REM     (TOTELEM - CHUNK * NBLK)     // 32

__device__ float g_part[NBLK * 3];
__device__ unsigned int g_count = 0;         // self-resetting via atomicInc wrap

__device__ __forceinline__ float ex2f(float x) {
    float y;
    asm("ex2.approx.ftz.f32 %0, %1;" : "=f"(y) : "f"(x));
    return y;
}

#define SL2E (30.0f * 1.44269504088896340736f)   // S * log2(e)

// Sum of exp(S*x) over score[lo, hi), strided across the block.
__device__ __forceinline__ float seg_sum(const float* __restrict__ score,
                                         int lo, int hi, int tid)
{
    const float* __restrict__ p = score + lo;
    int len = hi - lo;

    float s0 = 0.f, s1 = 0.f, s2 = 0.f, s3 = 0.f;

    int peel = (4 - (lo & 3)) & 3;
    if (peel > len) peel = len;
    if (tid < peel) s0 += ex2f(SL2E * p[tid]);

    int n4 = (len - peel) >> 2;
    const float4* __restrict__ q = (const float4*)(p + peel);

    int i = tid;
    for (; i + BLK < n4; i += 2 * BLK) {
        float4 a = q[i];
        float4 b = q[i + BLK];
        s0 += ex2f(SL2E * a.x); s1 += ex2f(SL2E * a.y);
        s2 += ex2f(SL2E * a.z); s3 += ex2f(SL2E * a.w);
        s0 += ex2f(SL2E * b.x); s1 += ex2f(SL2E * b.y);
        s2 += ex2f(SL2E * b.z); s3 += ex2f(SL2E * b.w);
    }
    for (; i < n4; i += BLK) {
        float4 a = q[i];
        s0 += ex2f(SL2E * a.x); s1 += ex2f(SL2E * a.y);
        s2 += ex2f(SL2E * a.z); s3 += ex2f(SL2E * a.w);
    }
    int done = peel + 4 * n4;
    if (tid < len - done) s0 += ex2f(SL2E * p[done + tid]);

    return (s0 + s1) + (s2 + s3);
}

__global__ __launch_bounds__(BLK) void amsm_kernel(
    const float* __restrict__ score,
    const int* __restrict__ labels,
    float* __restrict__ out)
{
    const int b   = blockIdx.x;
    const int tid = threadIdx.x;

    const int begin = b * CHUNK + (b < REM ? b : REM);
    const int end   = begin + CHUNK + (b < REM ? 1 : 0);
    const int r0    = begin / CCOLS;

    // A range of <= CHUNK+1 elements spans at most 3 rows.
    float part[3] = {0.f, 0.f, 0.f};
    int lo = begin;
    while (lo < end) {
        int r = lo / CCOLS;
        int rowend = (r + 1) * CCOLS;
        int hi = rowend < end ? rowend : end;
        part[r - r0] += seg_sum(score, lo, hi, tid);
        lo = hi;
    }

    // Block-reduce each of the 3 slots; thread 0 writes all 3 (zeros for unused
    // slots -> no stale state across graph replays).
    __shared__ float red[BLK];
    __shared__ float fin[3];
    #pragma unroll
    for (int k = 0; k < 3; k++) {
        red[tid] = part[k];
        __syncthreads();
        #pragma unroll
        for (int off = BLK / 2; off >= 32; off >>= 1) {
            if (tid < off) red[tid] += red[tid + off];
            __syncthreads();
        }
        if (tid < 32) {
            float v = red[tid];
            #pragma unroll
            for (int off = 16; off > 0; off >>= 1)
                v += __shfl_down_sync(0xFFFFFFFFu, v, off);
            if (tid == 0) fin[k] = v;
        }
        __syncthreads();
    }

    __shared__ unsigned s_last;
    if (tid == 0) {
        g_part[b * 3 + 0] = fin[0];
        g_part[b * 3 + 1] = fin[1];
        g_part[b * 3 + 2] = fin[2];
        __threadfence();
        unsigned old = atomicInc(&g_count, NBLK - 1);   // wraps -> self-reset
        s_last = (old == NBLK - 1) ? 1u : 0u;
    }
    __syncthreads();

    if (!s_last) return;

    // ---- Last block: gather partials, per-row epilogue, mean ----
    __shared__ float rowsum[NROWS];
    for (int r = tid; r < NROWS; r += BLK) rowsum[r] = 0.f;
    __syncthreads();

    volatile float* gp = g_part;
    for (int blk = tid; blk < NBLK; blk += BLK) {
        int bb = blk * CHUNK + (blk < REM ? blk : REM);
        int fr = bb / CCOLS;
        float p0 = gp[blk * 3 + 0];
        float p1 = gp[blk * 3 + 1];
        float p2 = gp[blk * 3 + 2];
        atomicAdd(&rowsum[fr], p0);
        if (p1 != 0.f && fr + 1 < NROWS) atomicAdd(&rowsum[fr + 1], p1);
        if (p2 != 0.f && fr + 2 < NROWS) atomicAdd(&rowsum[fr + 2], p2);
    }
    __syncthreads();

    double acc = 0.0;
    for (int r = tid; r < NROWS; r += BLK) {
        int lab = labels[r] & 1;
        float m = lab ? 0.4f : 0.1f;
        float t = __ldg(score + (size_t)r * CCOLS + lab);
        float num = 30.0f * (t - m);
        float excl = rowsum[r] - ex2f(SL2E * t);
        float denom = ex2f(num * 1.44269504088896340736f) + excl;
        acc += (double)(num - logf(denom));
    }

    __shared__ double dred[BLK];
    dred[tid] = acc;
    __syncthreads();
    #pragma unroll
    for (int off = BLK / 2; off > 0; off >>= 1) {
        if (tid < off) dred[tid] += dred[tid + off];
        __syncthreads();
    }
    if (tid == 0)
        out[0] = (float)(-dred[0] / (double)NROWS);
}

extern "C" void kernel_launch(void* const* d_in, const int* in_sizes, int n_in,
                              void* d_out, int out_size)
{
    const float* score = (const float*)d_in[0];
    const int* labels = (const int*)d_in[1];
    float* out = (float*)d_out;

    amsm_kernel<<<NBLK, BLK>>>(score, labels, out);
}

// round 5
// speedup vs baseline: 1.0745x; 1.0745x over previous
#include <cuda_runtime.h>
#include <cuda_bf16.h>

// AMSoftmaxLoss: score (2048 x 50257) fp32, labels (2048) int32 in {0,1}
// Persistent 1184 blocks; dynamic ticket over 16384 row-aligned tiles
// (8 segments per row). Last block folds partials + epilogue.

#define NROWS 2048
#define CCOLS 50257
#define NBLK  1184            // 148 SMs * 8 resident blocks
#define BLK   256
#define SEGS  8
#define SEGW  6283            // 8*6283 = 50264 >= 50257 (last seg = 6276)
#define NTILES (NROWS * SEGS) // 16384

__device__ float g_part[NTILES];
__device__ int g_ticket = 0;           // reset by finalize block each launch
__device__ unsigned int g_count = 0;   // self-resetting via atomicInc wrap

__device__ __forceinline__ float ex2f(float x) {
    float y;
    asm("ex2.approx.ftz.f32 %0, %1;" : "=f"(y) : "f"(x));
    return y;
}

#define SL2E (30.0f * 1.44269504088896340736f)   // S * log2(e)

// Sum of exp(S*x) over p[0, len), strided across the block.
__device__ __forceinline__ float tile_sum(const float* __restrict__ p,
                                          int len, int base_mod4, int tid)
{
    float s0 = 0.f, s1 = 0.f, s2 = 0.f, s3 = 0.f;

    int peel = (4 - base_mod4) & 3;
    if (peel > len) peel = len;
    if (tid < peel) s0 += ex2f(SL2E * p[tid]);

    int n4 = (len - peel) >> 2;
    const float4* __restrict__ q = (const float4*)(p + peel);

    int i = tid;
    for (; i + BLK < n4; i += 2 * BLK) {
        float4 a = q[i];
        float4 b = q[i + BLK];
        s0 += ex2f(SL2E * a.x); s1 += ex2f(SL2E * a.y);
        s2 += ex2f(SL2E * a.z); s3 += ex2f(SL2E * a.w);
        s0 += ex2f(SL2E * b.x); s1 += ex2f(SL2E * b.y);
        s2 += ex2f(SL2E * b.z); s3 += ex2f(SL2E * b.w);
    }
    for (; i < n4; i += BLK) {
        float4 a = q[i];
        s0 += ex2f(SL2E * a.x); s1 += ex2f(SL2E * a.y);
        s2 += ex2f(SL2E * a.z); s3 += ex2f(SL2E * a.w);
    }
    int done = peel + 4 * n4;
    if (tid < len - done) s0 += ex2f(SL2E * p[done + tid]);

    return (s0 + s1) + (s2 + s3);
}

__global__ __launch_bounds__(BLK) void amsm_kernel(
    const float* __restrict__ score,
    const int* __restrict__ labels,
    float* __restrict__ out)
{
    const int tid  = threadIdx.x;
    const int lane = tid & 31;
    const int wid  = tid >> 5;

    __shared__ volatile int s_tile;
    __shared__ float wsum[BLK / 32];

    if (tid == 0) s_tile = atomicAdd(&g_ticket, 1);
    __syncthreads();
    int t = s_tile;

    while (t < NTILES) {
        __syncthreads();                       // everyone copied t
        if (tid == 0) s_tile = atomicAdd(&g_ticket, 1);  // prefetch next

        const int r    = t >> 3;
        const int seg  = t & 7;
        const int col0 = seg * SEGW;
        const int len  = (seg == SEGS - 1) ? (CCOLS - col0) : SEGW;
        const int base = r * CCOLS + col0;     // fits in 32-bit? r*CCOLS up to 1.03e8 < 2^31 ok

        float v = tile_sum(score + (size_t)r * CCOLS + col0, len, base & 3, tid);

        // block reduction: warp shuffle, then first warp
        #pragma unroll
        for (int off = 16; off > 0; off >>= 1)
            v += __shfl_down_sync(0xFFFFFFFFu, v, off);
        if (lane == 0) wsum[wid] = v;
        __syncthreads();
        if (tid < BLK / 32) {
            float w = wsum[tid];
            #pragma unroll
            for (int off = BLK / 64; off > 0; off >>= 1)
                w += __shfl_down_sync(0xFFu, w, off);
            if (tid == 0) g_part[t] = w;
        }
        __syncthreads();                       // wsum reuse + s_tile ready
        t = s_tile;
    }

    __shared__ unsigned s_last;
    if (tid == 0) {
        __threadfence();
        unsigned old = atomicInc(&g_count, NBLK - 1);   // wraps -> self-reset
        s_last = (old == NBLK - 1) ? 1u : 0u;
    }
    __syncthreads();
    if (!s_last) return;

    // ---- Last block: fold partials, per-row epilogue, mean, reset ticket ----
    if (tid == 0) g_ticket = 0;                // next graph replay starts clean

    volatile float* gp = g_part;
    double acc = 0.0;
    for (int r = tid; r < NROWS; r += BLK) {
        float rs = 0.f;
        #pragma unroll
        for (int k = 0; k < SEGS; k++) rs += gp[r * SEGS + k];

        int lab = labels[r] & 1;
        float m = lab ? 0.4f : 0.1f;
        float tg = __ldg(score + (size_t)r * CCOLS + lab);
        float num = 30.0f * (tg - m);
        float excl = rs - ex2f(SL2E * tg);
        float denom = ex2f(num * 1.44269504088896340736f) + excl;
        acc += (double)(num - logf(denom));
    }

    __shared__ double dred[BLK];
    dred[tid] = acc;
    __syncthreads();
    #pragma unroll
    for (int off = BLK / 2; off > 0; off >>= 1) {
        if (tid < off) dred[tid] += dred[tid + off];
        __syncthreads();
    }
    if (tid == 0)
        out[0] = (float)(-dred[0] / (double)NROWS);
}

extern "C" void kernel_launch(void* const* d_in, const int* in_sizes, int n_in,
                              void* d_out, int out_size)
{
    const float* score = (const float*)d_in[0];
    const int* labels = (const int*)d_in[1];
    float* out = (float*)d_out;

    amsm_kernel<<<NBLK, BLK>>>(score, labels, out);
}